// round 9
// baseline (speedup 1.0000x reference)
#include <cuda_runtime.h>
#include <cuda_bf16.h>
#include <cuda_fp16.h>
#include <cstdint>

#define NROWS 8192
#define BHALF 4096
#define KDIM  128
#define NBLK  64
#define PCTAS  296           // persistent CTAs (2 per SM)

// Scratch (device globals — no allocation allowed in kernel_launch)
__device__ uint8_t g_X8[NROWS * KDIM];         // e4m3 copy of features
__device__ float g_sq[NROWS];                  // |x|^2 from fp8-rounded values
__device__ float g_row[NROWS];                 // full row sums of 8192x8192 kernel matrix
__device__ float g_logdiag[BHALF];             // log k12(i,i), fp32 path
__device__ float g_part[2];                    // partial sums for finalize
__device__ unsigned int g_cnt;                 // finalize block counter

static __device__ __forceinline__ uint32_t smem_u32(const void* p) {
    return (uint32_t)__cvta_generic_to_shared(p);
}

static __device__ __forceinline__ float rcp_approx(float x) {
    float r;
    asm("rcp.approx.ftz.f32 %0, %1;" : "=f"(r) : "f"(x));
    return r;
}

static __device__ __forceinline__ void cp_async16(uint32_t dst, const void* src) {
    asm volatile("cp.async.cg.shared.global [%0], [%1], 16;"
                 :: "r"(dst), "l"(src));
}
static __device__ __forceinline__ void cp_commit() {
    asm volatile("cp.async.commit_group;" ::: "memory");
}

// fp8 pack: lo = x, hi = y (cvt packs 2nd src operand into low half)
static __device__ __forceinline__ uint16_t f2_to_e4m3x2(float x, float y) {
    uint16_t r;
    asm("cvt.rn.satfinite.e4m3x2.f32 %0, %1, %2;" : "=h"(r) : "f"(y), "f"(x));
    return r;
}
static __device__ __forceinline__ float2 e4m3x2_to_f2(uint16_t q) {
    uint32_t h2;
    asm("cvt.rn.f16x2.e4m3x2 %0, %1;" : "=r"(h2) : "h"(q));
    return __half22float2(*(__half2*)&h2);
}

// ---------------------------------------------------------------------------
// K1: fused prep + diag. One warp per pair (i, i+4096).
// ---------------------------------------------------------------------------
__global__ void prep_kernel(const float* __restrict__ feat) {
    int w = threadIdx.x >> 5;
    int lane = threadIdx.x & 31;
    int p = blockIdx.x * 8 + w;           // 0..4095
    if (blockIdx.x == 0 && threadIdx.x == 0) {
        g_part[0] = 0.f; g_part[1] = 0.f; g_cnt = 0u;
    }
    if (p >= BHALF) return;
    float4 v1 = ((const float4*)(feat + (size_t)p * KDIM))[lane];
    float4 v2 = ((const float4*)(feat + (size_t)(p + BHALF) * KDIM))[lane];

    uint16_t q1a = f2_to_e4m3x2(v1.x, v1.y), q1b = f2_to_e4m3x2(v1.z, v1.w);
    uint16_t q2a = f2_to_e4m3x2(v2.x, v2.y), q2b = f2_to_e4m3x2(v2.z, v2.w);
    ((uint32_t*)(g_X8 + (size_t)p * KDIM))[lane] = (uint32_t)q1a | ((uint32_t)q1b << 16);
    ((uint32_t*)(g_X8 + (size_t)(p + BHALF) * KDIM))[lane] = (uint32_t)q2a | ((uint32_t)q2b << 16);

    float2 r1a = e4m3x2_to_f2(q1a), r1b = e4m3x2_to_f2(q1b);
    float2 r2a = e4m3x2_to_f2(q2a), r2b = e4m3x2_to_f2(q2b);
    float sb1 = r1a.x * r1a.x + r1a.y * r1a.y + r1b.x * r1b.x + r1b.y * r1b.y;
    float sb2 = r2a.x * r2a.x + r2a.y * r2a.y + r2b.x * r2b.x + r2b.y * r2b.y;
    float t1 = v1.x * v1.x + v1.y * v1.y + v1.z * v1.z + v1.w * v1.w;
    float t2 = v2.x * v2.x + v2.y * v2.y + v2.z * v2.z + v2.w * v2.w;
    float sd = v1.x * v2.x + v1.y * v2.y + v1.z * v2.z + v1.w * v2.w;

#pragma unroll
    for (int off = 16; off > 0; off >>= 1) {
        sb1 += __shfl_xor_sync(0xffffffff, sb1, off);
        sb2 += __shfl_xor_sync(0xffffffff, sb2, off);
        t1  += __shfl_xor_sync(0xffffffff, t1, off);
        t2  += __shfl_xor_sync(0xffffffff, t2, off);
        sd  += __shfl_xor_sync(0xffffffff, sd, off);
    }
    if (lane == 0) {
        g_sq[p] = sb1;
        g_sq[p + BHALF] = sb2;
        g_row[p] = 0.f;
        g_row[p + BHALF] = 0.f;
        float d2v = fmaxf(t1 + t2 - 2.f * sd, 0.f);
        g_logdiag[p] = -log1pf(d2v);
    }
}

// ---------------------------------------------------------------------------
// K2: persistent, software-pipelined fp8 pairwise kernel, half-tile
// interleaved. Each 128x128 tile is processed as two 128x64 n-halves:
// half1's ldmatrix+mma loop carries half0's epilogue chunks so tensor/LSU
// work overlaps fma/MUFU work within each warp. Scalar mov-free epilogue.
// ---------------------------------------------------------------------------
#define LDS_STRIDE_B 144   // bytes per smem row: 128 data + 16 pad
#define TILE_BYTES (128 * LDS_STRIDE_B)        // 18432
#define PAIR_SMEM_BYTES (3 * TILE_BYTES)       // A + 2x B = 55296

__global__ void __launch_bounds__(256, 2) pair_kernel() {
    extern __shared__ __align__(16) char dynsm[];
    const uint32_t abase = smem_u32(dynsm);
    const uint32_t bbase0 = abase + TILE_BYTES;
    __shared__ float s_a[128];        // |x|^2 for A rows (raw)
    __shared__ float s_bb[2][128];    // |y|^2 for B rows (raw), per buffer

    const int tid = threadIdx.x;
    const int lane = tid & 31;
    const int wid = tid >> 5;

    // ---- chunk of tiles for this CTA ----
    const int b = blockIdx.x;
    const int start = b * 7 + (b < 8 ? b : 8);
    const int cnt = 7 + (b < 8 ? 1 : 0);
    int bi = 0, rem = start;
    while (rem >= NBLK - bi) { rem -= NBLK - bi; bi++; }
    int bj = bi + rem;

    auto issue_B = [&](int blk, int buf) {
        const char* g = (const char*)(g_X8 + (size_t)blk * 128 * KDIM);
        uint32_t sb = bbase0 + buf * TILE_BYTES;
#pragma unroll
        for (int it = 0; it < 4; it++) {
            int idx = tid + it * 256;          // 0..1023 (16B chunks)
            int r = idx >> 3, c = idx & 7;
            cp_async16(sb + r * LDS_STRIDE_B + c * 16, g + r * 128 + c * 16);
        }
        if (tid < 32)
            cp_async16(smem_u32(&s_bb[buf][0]) + tid * 16,
                       (const char*)(g_sq + blk * 128) + tid * 16);
    };
    auto issue_A = [&](int blk) {
        const char* g = (const char*)(g_X8 + (size_t)blk * 128 * KDIM);
#pragma unroll
        for (int it = 0; it < 4; it++) {
            int idx = tid + it * 256;
            int r = idx >> 3, c = idx & 7;
            cp_async16(abase + r * LDS_STRIDE_B + c * 16, g + r * 128 + c * 16);
        }
        if (tid < 32)
            cp_async16(smem_u32(&s_a[0]) + tid * 16,
                       (const char*)(g_sq + blk * 128) + tid * 16);
    };

    // ---- warp tiling: 4 (m) x 2 (n); warp tile = 32 x 64, split in 2 halves
    const int rowbase = (wid & 3) * 32;
    const int colbase = (wid >> 2) * 64;
    const int lr = lane & 15;
    const int lc = lane >> 4;
    uint32_t aoff[2];
    uint32_t brel[4];
#pragma unroll
    for (int mi = 0; mi < 2; mi++)
        aoff[mi] = abase + (uint32_t)((rowbase + mi * 16 + lr) * LDS_STRIDE_B + lc * 16);
#pragma unroll
    for (int nq = 0; nq < 4; nq++)
        brel[nq] = (uint32_t)((colbase + nq * 16 + lr) * LDS_STRIDE_B + lc * 16);

    const int qr = lane >> 2;
    const int qc = (lane & 3) * 2;

    // ---- prime: A(bi) + B(bj) into buf 0 ----
    issue_A(bi);
    issue_B(bj, 0);
    cp_commit();
    bool need_cur = false;

    for (int i = 0; i < cnt; i++) {
        const int cur = i & 1;
        int nbi = bi, nbj = bj + 1;
        if (nbj == NBLK) { nbi++; nbj = nbi; }
        const bool have_next = (i + 1 < cnt);
        const bool same_bi = have_next && (nbi == bi);

        if (i > 0) __syncthreads();   // nobody still reads any buffer
        if (need_cur) {               // bi crossing: load A(bi)+B(bj,cur)
            issue_A(bi);
            issue_B(bj, cur);
            cp_commit();
        }
        if (same_bi) {                // prefetch next B during compute
            issue_B(nbj, cur ^ 1);
            cp_commit();
            asm volatile("cp.async.wait_group 1;" ::: "memory");
        } else {
            asm volatile("cp.async.wait_group 0;" ::: "memory");
        }
        __syncthreads();
        need_cur = have_next && (nbi != bi);

        const uint32_t bb = bbase0 + cur * TILE_BYTES;
        const float* s_b = s_bb[cur];
        const bool offdiag = (bi != bj);

        // row-norm terms (constant across the tile)
        float av[2][2];
#pragma unroll
        for (int mi = 0; mi < 2; mi++) {
            av[mi][0] = 1.f + s_a[rowbase + mi * 16 + qr];
            av[mi][1] = 1.f + s_a[rowbase + mi * 16 + qr + 8];
        }
        float rs[2][2] = {{0.f, 0.f}, {0.f, 0.f}};

        // scalar epilogue chunk for one ni (8 columns) of a given half
        auto epi = [&](float (&acc)[2][4][4], int nil, int half) {
            int col = colbase + half * 32 + nil * 8;
            float b0 = s_b[col + qc];
            float b1 = s_b[col + qc + 1];
            float cs0 = 0.f, cs1 = 0.f;
#pragma unroll
            for (int mi = 0; mi < 2; mi++) {
                float k00 = rcp_approx(fmaf(acc[mi][nil][0], -2.f, av[mi][0] + b0));
                float k01 = rcp_approx(fmaf(acc[mi][nil][1], -2.f, av[mi][0] + b1));
                float k10 = rcp_approx(fmaf(acc[mi][nil][2], -2.f, av[mi][1] + b0));
                float k11 = rcp_approx(fmaf(acc[mi][nil][3], -2.f, av[mi][1] + b1));
                rs[mi][0] += k00 + k01;
                rs[mi][1] += k10 + k11;
                cs0 += k00 + k10;
                cs1 += k01 + k11;
            }
            if (offdiag) {
                cs0 += __shfl_xor_sync(0xffffffff, cs0, 4);
                cs1 += __shfl_xor_sync(0xffffffff, cs1, 4);
                cs0 += __shfl_xor_sync(0xffffffff, cs0, 8);
                cs1 += __shfl_xor_sync(0xffffffff, cs1, 8);
                cs0 += __shfl_xor_sync(0xffffffff, cs0, 16);
                cs1 += __shfl_xor_sync(0xffffffff, cs1, 16);
                if (lane < 4) {
                    int cg = bj * 128 + col + qc;
                    atomicAdd(g_row + cg, cs0);
                    atomicAdd(g_row + cg + 1, cs1);
                }
            }
        };

        // one ks-step of mma for a half (nq0 = 2*half)
        auto mma_step = [&](float (&acc)[2][4][4], int ks, int half) {
            uint32_t a[2][4];
#pragma unroll
            for (int mi = 0; mi < 2; mi++) {
                asm volatile("ldmatrix.sync.aligned.m8n8.x4.shared.b16 {%0,%1,%2,%3}, [%4];"
                             : "=r"(a[mi][0]), "=r"(a[mi][1]), "=r"(a[mi][2]), "=r"(a[mi][3])
                             : "r"(aoff[mi] + ks * 32));
            }
            uint32_t bfr[4][2];
#pragma unroll
            for (int q = 0; q < 2; q++) {
                uint32_t r0, r1, r2, r3;
                asm volatile("ldmatrix.sync.aligned.m8n8.x4.shared.b16 {%0,%1,%2,%3}, [%4];"
                             : "=r"(r0), "=r"(r1), "=r"(r2), "=r"(r3)
                             : "r"(bb + brel[2 * half + q] + ks * 32));
                bfr[q * 2 + 0][0] = r0; bfr[q * 2 + 1][0] = r1;
                bfr[q * 2 + 0][1] = r2; bfr[q * 2 + 1][1] = r3;
            }
#pragma unroll
            for (int mi = 0; mi < 2; mi++)
#pragma unroll
                for (int ni = 0; ni < 4; ni++) {
                    asm volatile(
                        "mma.sync.aligned.m16n8k32.row.col.f32.e4m3.e4m3.f32 "
                        "{%0,%1,%2,%3}, {%4,%5,%6,%7}, {%8,%9}, {%0,%1,%2,%3};"
                        : "+f"(acc[mi][ni][0]), "+f"(acc[mi][ni][1]),
                          "+f"(acc[mi][ni][2]), "+f"(acc[mi][ni][3])
                        : "r"(a[mi][0]), "r"(a[mi][1]), "r"(a[mi][2]), "r"(a[mi][3]),
                          "r"(bfr[ni][0]), "r"(bfr[ni][1]));
                }
        };

        float acc0[2][4][4], acc1[2][4][4];
#pragma unroll
        for (int mi = 0; mi < 2; mi++)
#pragma unroll
            for (int ni = 0; ni < 4; ni++)
#pragma unroll
                for (int r = 0; r < 4; r++) { acc0[mi][ni][r] = 0.f; acc1[mi][ni][r] = 0.f; }

        // half0 mma
#pragma unroll
        for (int ks = 0; ks < 4; ks++) mma_step(acc0, ks, 0);
        // half1 mma with half0 epilogue interleaved (tensor/LSU || fma/MUFU)
#pragma unroll
        for (int ks = 0; ks < 4; ks++) {
            mma_step(acc1, ks, 1);
            epi(acc0, ks, 0);
        }
        // half1 epilogue
#pragma unroll
        for (int ni = 0; ni < 4; ni++) epi(acc1, ni, 1);

        // row-sum reduction + atomics
#pragma unroll
        for (int mi = 0; mi < 2; mi++) {
            float rs0 = rs[mi][0], rs1 = rs[mi][1];
            rs0 += __shfl_xor_sync(0xffffffff, rs0, 1);
            rs1 += __shfl_xor_sync(0xffffffff, rs1, 1);
            rs0 += __shfl_xor_sync(0xffffffff, rs0, 2);
            rs1 += __shfl_xor_sync(0xffffffff, rs1, 2);
            if ((lane & 3) == 0) {
                int r0 = bi * 128 + rowbase + mi * 16 + qr;
                atomicAdd(g_row + r0, rs0);
                atomicAdd(g_row + r0 + 8, rs1);
            }
        }

        bi = nbi; bj = nbj;
    }
}

// ---------------------------------------------------------------------------
// K3: parallel finalize.
// ---------------------------------------------------------------------------
__global__ void finalize_kernel(float* out) {
    const int tid = threadIdx.x;
    const int b = blockIdx.x;
    int row = b * 512 + tid;                 // 16*512 = 8192
    float an = __logf(g_row[row] - 1.0f);
    float ap = (tid < 256) ? g_logdiag[b * 256 + tid] : 0.f;
#pragma unroll
    for (int off = 16; off > 0; off >>= 1) {
        an += __shfl_xor_sync(0xffffffff, an, off);
        ap += __shfl_xor_sync(0xffffffff, ap, off);
    }
    __shared__ float sn[16], sp[16];
    int wid = tid >> 5, lane = tid & 31;
    if (lane == 0) { sn[wid] = an; sp[wid] = ap; }
    __syncthreads();
    if (tid == 0) {
        float tn = 0.f, tp = 0.f;
#pragma unroll
        for (int i = 0; i < 16; i++) { tn += sn[i]; tp += sp[i]; }
        atomicAdd(&g_part[0], tn);
        atomicAdd(&g_part[1], tp);
        __threadfence();
        unsigned int done = atomicAdd(&g_cnt, 1u);
        if (done == 15u) {
            float neg = *((volatile float*)&g_part[0]) / (2.0f * (float)BHALF);
            float pos = *((volatile float*)&g_part[1]) / (float)BHALF;
            out[0] = neg - pos;   // -(pos - neg)
        }
    }
}

// ---------------------------------------------------------------------------
extern "C" void kernel_launch(void* const* d_in, const int* in_sizes, int n_in,
                              void* d_out, int out_size) {
    const float* feat = (const float*)d_in[0];
    float* out = (float*)d_out;

    cudaFuncSetAttribute(pair_kernel,
                         cudaFuncAttributeMaxDynamicSharedMemorySize,
                         PAIR_SMEM_BYTES);

    prep_kernel<<<BHALF / 8, 256>>>(feat);
    pair_kernel<<<PCTAS, 256, PAIR_SMEM_BYTES>>>();
    finalize_kernel<<<16, 512>>>(out);
}

// round 10
// speedup vs baseline: 1.0375x; 1.0375x over previous
#include <cuda_runtime.h>
#include <cuda_bf16.h>
#include <cuda_fp16.h>
#include <cstdint>

#define NROWS 8192
#define BHALF 4096
#define KDIM  128
#define NBLK  64
#define PCTAS  296           // persistent CTAs (2 per SM)

// Scratch (device globals — no allocation allowed in kernel_launch)
__device__ uint8_t g_X8[NROWS * KDIM];         // e4m3 copy of features
__device__ float g_sq[NROWS];                  // |x|^2 from fp8-rounded values
__device__ float g_row[NROWS];                 // full row sums of 8192x8192 kernel matrix
__device__ float g_logdiag[BHALF];             // log k12(i,i), fp32 path
__device__ float g_part[2];                    // partial sums for finalize
__device__ unsigned int g_cnt;                 // finalize block counter

static __device__ __forceinline__ uint32_t smem_u32(const void* p) {
    return (uint32_t)__cvta_generic_to_shared(p);
}

static __device__ __forceinline__ float rcp_approx(float x) {
    float r;
    asm("rcp.approx.ftz.f32 %0, %1;" : "=f"(r) : "f"(x));
    return r;
}

static __device__ __forceinline__ void cp_async16(uint32_t dst, const void* src) {
    asm volatile("cp.async.cg.shared.global [%0], [%1], 16;"
                 :: "r"(dst), "l"(src));
}
static __device__ __forceinline__ void cp_commit() {
    asm volatile("cp.async.commit_group;" ::: "memory");
}

// fp8 pack: lo = x, hi = y (cvt packs 2nd src operand into low half)
static __device__ __forceinline__ uint16_t f2_to_e4m3x2(float x, float y) {
    uint16_t r;
    asm("cvt.rn.satfinite.e4m3x2.f32 %0, %1, %2;" : "=h"(r) : "f"(y), "f"(x));
    return r;
}
static __device__ __forceinline__ float2 e4m3x2_to_f2(uint16_t q) {
    uint32_t h2;
    asm("cvt.rn.f16x2.e4m3x2 %0, %1;" : "=r"(h2) : "h"(q));
    return __half22float2(*(__half2*)&h2);
}

// ---------------------------------------------------------------------------
// K1: fused prep + diag. One warp per pair (i, i+4096).
// ---------------------------------------------------------------------------
__global__ void prep_kernel(const float* __restrict__ feat) {
    int w = threadIdx.x >> 5;
    int lane = threadIdx.x & 31;
    int p = blockIdx.x * 8 + w;           // 0..4095
    if (blockIdx.x == 0 && threadIdx.x == 0) {
        g_part[0] = 0.f; g_part[1] = 0.f; g_cnt = 0u;
    }
    if (p >= BHALF) return;
    float4 v1 = ((const float4*)(feat + (size_t)p * KDIM))[lane];
    float4 v2 = ((const float4*)(feat + (size_t)(p + BHALF) * KDIM))[lane];

    uint16_t q1a = f2_to_e4m3x2(v1.x, v1.y), q1b = f2_to_e4m3x2(v1.z, v1.w);
    uint16_t q2a = f2_to_e4m3x2(v2.x, v2.y), q2b = f2_to_e4m3x2(v2.z, v2.w);
    ((uint32_t*)(g_X8 + (size_t)p * KDIM))[lane] = (uint32_t)q1a | ((uint32_t)q1b << 16);
    ((uint32_t*)(g_X8 + (size_t)(p + BHALF) * KDIM))[lane] = (uint32_t)q2a | ((uint32_t)q2b << 16);

    float2 r1a = e4m3x2_to_f2(q1a), r1b = e4m3x2_to_f2(q1b);
    float2 r2a = e4m3x2_to_f2(q2a), r2b = e4m3x2_to_f2(q2b);
    float sb1 = r1a.x * r1a.x + r1a.y * r1a.y + r1b.x * r1b.x + r1b.y * r1b.y;
    float sb2 = r2a.x * r2a.x + r2a.y * r2a.y + r2b.x * r2b.x + r2b.y * r2b.y;
    float t1 = v1.x * v1.x + v1.y * v1.y + v1.z * v1.z + v1.w * v1.w;
    float t2 = v2.x * v2.x + v2.y * v2.y + v2.z * v2.z + v2.w * v2.w;
    float sd = v1.x * v2.x + v1.y * v2.y + v1.z * v2.z + v1.w * v2.w;

#pragma unroll
    for (int off = 16; off > 0; off >>= 1) {
        sb1 += __shfl_xor_sync(0xffffffff, sb1, off);
        sb2 += __shfl_xor_sync(0xffffffff, sb2, off);
        t1  += __shfl_xor_sync(0xffffffff, t1, off);
        t2  += __shfl_xor_sync(0xffffffff, t2, off);
        sd  += __shfl_xor_sync(0xffffffff, sd, off);
    }
    if (lane == 0) {
        g_sq[p] = sb1;
        g_sq[p + BHALF] = sb2;
        g_row[p] = 0.f;
        g_row[p + BHALF] = 0.f;
        float d2v = fmaxf(t1 + t2 - 2.f * sd, 0.f);
        g_logdiag[p] = -log1pf(d2v);
    }
}

// ---------------------------------------------------------------------------
// K2: persistent fp8 pairwise kernel. 296 CTAs x 7-8 upper-triangle 128x128
// tiles, bi-major; A resident per chunk; B in a 3-deep cp.async ring so the
// steady state needs only ONE __syncthreads per tile (prefetch for tile i+1
// targets ring slot (i+1)%3, last read at tile i-2 — every warp passed the
// post-wait sync of tile i-1 after that epilogue, so no concurrent readers).
// mma.sync m16n8k32 e4m3, scalar mov-free Cauchy epilogue, straight phases.
// ---------------------------------------------------------------------------
#define LDS_STRIDE_B 144   // bytes per smem row: 128 data + 16 pad
#define TILE_BYTES (128 * LDS_STRIDE_B)        // 18432
#define PAIR_SMEM_BYTES (4 * TILE_BYTES)       // A + 3-ring B = 73728

__global__ void __launch_bounds__(256, 2) pair_kernel() {
    extern __shared__ __align__(16) char dynsm[];
    const uint32_t abase = smem_u32(dynsm);
    const uint32_t bbase0 = abase + TILE_BYTES;
    __shared__ float s_a[128];        // |x|^2 for A rows (raw)
    __shared__ float s_bb[3][128];    // |y|^2 for B rows (raw), per ring slot

    const int tid = threadIdx.x;
    const int lane = tid & 31;
    const int wid = tid >> 5;

    // ---- chunk of tiles for this CTA ----
    const int b = blockIdx.x;
    const int start = b * 7 + (b < 8 ? b : 8);
    const int cnt = 7 + (b < 8 ? 1 : 0);
    int bi = 0, rem = start;
    while (rem >= NBLK - bi) { rem -= NBLK - bi; bi++; }
    int bj = bi + rem;

    auto issue_B = [&](int blk, int buf) {
        const char* g = (const char*)(g_X8 + (size_t)blk * 128 * KDIM);
        uint32_t sb = bbase0 + buf * TILE_BYTES;
#pragma unroll
        for (int it = 0; it < 4; it++) {
            int idx = tid + it * 256;          // 0..1023 (16B chunks)
            int r = idx >> 3, c = idx & 7;
            cp_async16(sb + r * LDS_STRIDE_B + c * 16, g + r * 128 + c * 16);
        }
        if (tid < 32)
            cp_async16(smem_u32(&s_bb[buf][0]) + tid * 16,
                       (const char*)(g_sq + blk * 128) + tid * 16);
    };
    auto issue_A = [&](int blk) {
        const char* g = (const char*)(g_X8 + (size_t)blk * 128 * KDIM);
#pragma unroll
        for (int it = 0; it < 4; it++) {
            int idx = tid + it * 256;
            int r = idx >> 3, c = idx & 7;
            cp_async16(abase + r * LDS_STRIDE_B + c * 16, g + r * 128 + c * 16);
        }
        if (tid < 32)
            cp_async16(smem_u32(&s_a[0]) + tid * 16,
                       (const char*)(g_sq + blk * 128) + tid * 16);
    };

    // ---- warp tiling: 4 (m) x 2 (n); warp tile = 32 x 64 ----
    const int rowbase = (wid & 3) * 32;
    const int colbase = (wid >> 2) * 64;
    const int lr = lane & 15;
    const int lc = lane >> 4;
    uint32_t aoff[2];
    uint32_t brel[4];
#pragma unroll
    for (int mi = 0; mi < 2; mi++)
        aoff[mi] = abase + (uint32_t)((rowbase + mi * 16 + lr) * LDS_STRIDE_B + lc * 16);
#pragma unroll
    for (int nq = 0; nq < 4; nq++)
        brel[nq] = (uint32_t)((colbase + nq * 16 + lr) * LDS_STRIDE_B + lc * 16);

    const int qr = lane >> 2;
    const int qc = (lane & 3) * 2;

    // ring slot for tile i is i % 3
    int cur = 0;
    issue_A(bi);
    issue_B(bj, 0);
    cp_commit();
    bool need_cur = false;

    for (int i = 0; i < cnt; i++) {
        int nbi = bi, nbj = bj + 1;
        if (nbj == NBLK) { nbi++; nbj = nbi; }
        const bool have_next = (i + 1 < cnt);
        const bool same_bi = have_next && (nbi == bi);
        const int nxt = (cur + 1 == 3) ? 0 : cur + 1;

        if (need_cur) {               // bi crossing: A + B(cur) not yet loaded
            __syncthreads();          // all warps done with sA and old buffers
            issue_A(bi);
            issue_B(bj, cur);
            cp_commit();
        }
        if (same_bi) {                // prefetch next B during this tile
            issue_B(nbj, nxt);
            cp_commit();
            asm volatile("cp.async.wait_group 1;" ::: "memory");
        } else {
            asm volatile("cp.async.wait_group 0;" ::: "memory");
        }
        __syncthreads();              // single steady-state barrier per tile
        need_cur = have_next && (nbi != bi);

        const uint32_t bb = bbase0 + cur * TILE_BYTES;
        const float* s_b = s_bb[cur];
        const bool offdiag = (bi != bj);

        // ---- mma over K=128 fp8 (4 steps of 32) ----
        float acc[2][8][4];
#pragma unroll
        for (int mi = 0; mi < 2; mi++)
#pragma unroll
            for (int ni = 0; ni < 8; ni++)
#pragma unroll
                for (int r = 0; r < 4; r++) acc[mi][ni][r] = 0.f;

#pragma unroll
        for (int ks = 0; ks < 4; ks++) {
            uint32_t a[2][4];
            uint32_t bfr[8][2];
#pragma unroll
            for (int mi = 0; mi < 2; mi++) {
                asm volatile("ldmatrix.sync.aligned.m8n8.x4.shared.b16 {%0,%1,%2,%3}, [%4];"
                             : "=r"(a[mi][0]), "=r"(a[mi][1]), "=r"(a[mi][2]), "=r"(a[mi][3])
                             : "r"(aoff[mi] + ks * 32));
            }
#pragma unroll
            for (int nq = 0; nq < 4; nq++) {
                uint32_t r0, r1, r2, r3;
                asm volatile("ldmatrix.sync.aligned.m8n8.x4.shared.b16 {%0,%1,%2,%3}, [%4];"
                             : "=r"(r0), "=r"(r1), "=r"(r2), "=r"(r3)
                             : "r"(bb + brel[nq] + ks * 32));
                bfr[nq * 2 + 0][0] = r0; bfr[nq * 2 + 1][0] = r1;
                bfr[nq * 2 + 0][1] = r2; bfr[nq * 2 + 1][1] = r3;
            }
#pragma unroll
            for (int mi = 0; mi < 2; mi++)
#pragma unroll
                for (int ni = 0; ni < 8; ni++) {
                    asm volatile(
                        "mma.sync.aligned.m16n8k32.row.col.f32.e4m3.e4m3.f32 "
                        "{%0,%1,%2,%3}, {%4,%5,%6,%7}, {%8,%9}, {%0,%1,%2,%3};"
                        : "+f"(acc[mi][ni][0]), "+f"(acc[mi][ni][1]),
                          "+f"(acc[mi][ni][2]), "+f"(acc[mi][ni][3])
                        : "r"(a[mi][0]), "r"(a[mi][1]), "r"(a[mi][2]), "r"(a[mi][3]),
                          "r"(bfr[ni][0]), "r"(bfr[ni][1]));
                }
        }

        // ---- scalar mov-free epilogue: k = 1/(1 + |x|^2 + |y|^2 - 2 x.y) ----
        float av0[2], av1[2];
#pragma unroll
        for (int mi = 0; mi < 2; mi++) {
            av0[mi] = 1.f + s_a[rowbase + mi * 16 + qr];
            av1[mi] = 1.f + s_a[rowbase + mi * 16 + qr + 8];
        }
        float rs[2][2] = {{0.f, 0.f}, {0.f, 0.f}};

#pragma unroll
        for (int ni = 0; ni < 8; ni++) {
            float b0 = s_b[colbase + ni * 8 + qc];
            float b1 = s_b[colbase + ni * 8 + qc + 1];
            float cs0 = 0.f, cs1 = 0.f;
#pragma unroll
            for (int mi = 0; mi < 2; mi++) {
                float k00 = rcp_approx(fmaf(acc[mi][ni][0], -2.f, av0[mi] + b0));
                float k01 = rcp_approx(fmaf(acc[mi][ni][1], -2.f, av0[mi] + b1));
                float k10 = rcp_approx(fmaf(acc[mi][ni][2], -2.f, av1[mi] + b0));
                float k11 = rcp_approx(fmaf(acc[mi][ni][3], -2.f, av1[mi] + b1));
                rs[mi][0] += k00 + k01;
                rs[mi][1] += k10 + k11;
                cs0 += k00 + k10;
                cs1 += k01 + k11;
            }
            if (offdiag) {
                cs0 += __shfl_xor_sync(0xffffffff, cs0, 4);
                cs1 += __shfl_xor_sync(0xffffffff, cs1, 4);
                cs0 += __shfl_xor_sync(0xffffffff, cs0, 8);
                cs1 += __shfl_xor_sync(0xffffffff, cs1, 8);
                cs0 += __shfl_xor_sync(0xffffffff, cs0, 16);
                cs1 += __shfl_xor_sync(0xffffffff, cs1, 16);
                if (lane < 4) {
                    int cg = bj * 128 + colbase + ni * 8 + qc;
                    atomicAdd(g_row + cg, cs0);
                    atomicAdd(g_row + cg + 1, cs1);
                }
            }
        }
#pragma unroll
        for (int mi = 0; mi < 2; mi++) {
            float rs0 = rs[mi][0], rs1 = rs[mi][1];
            rs0 += __shfl_xor_sync(0xffffffff, rs0, 1);
            rs1 += __shfl_xor_sync(0xffffffff, rs1, 1);
            rs0 += __shfl_xor_sync(0xffffffff, rs0, 2);
            rs1 += __shfl_xor_sync(0xffffffff, rs1, 2);
            if ((lane & 3) == 0) {
                int r0 = bi * 128 + rowbase + mi * 16 + qr;
                atomicAdd(g_row + r0, rs0);
                atomicAdd(g_row + r0 + 8, rs1);
            }
        }

        bi = nbi; bj = nbj;
        cur = nxt;
    }
}

// ---------------------------------------------------------------------------
// K3: parallel finalize.
// ---------------------------------------------------------------------------
__global__ void finalize_kernel(float* out) {
    const int tid = threadIdx.x;
    const int b = blockIdx.x;
    int row = b * 512 + tid;                 // 16*512 = 8192
    float an = __logf(g_row[row] - 1.0f);
    float ap = (tid < 256) ? g_logdiag[b * 256 + tid] : 0.f;
#pragma unroll
    for (int off = 16; off > 0; off >>= 1) {
        an += __shfl_xor_sync(0xffffffff, an, off);
        ap += __shfl_xor_sync(0xffffffff, ap, off);
    }
    __shared__ float sn[16], sp[16];
    int wid = tid >> 5, lane = tid & 31;
    if (lane == 0) { sn[wid] = an; sp[wid] = ap; }
    __syncthreads();
    if (tid == 0) {
        float tn = 0.f, tp = 0.f;
#pragma unroll
        for (int i = 0; i < 16; i++) { tn += sn[i]; tp += sp[i]; }
        atomicAdd(&g_part[0], tn);
        atomicAdd(&g_part[1], tp);
        __threadfence();
        unsigned int done = atomicAdd(&g_cnt, 1u);
        if (done == 15u) {
            float neg = *((volatile float*)&g_part[0]) / (2.0f * (float)BHALF);
            float pos = *((volatile float*)&g_part[1]) / (float)BHALF;
            out[0] = neg - pos;   // -(pos - neg)
        }
    }
}

// ---------------------------------------------------------------------------
extern "C" void kernel_launch(void* const* d_in, const int* in_sizes, int n_in,
                              void* d_out, int out_size) {
    const float* feat = (const float*)d_in[0];
    float* out = (float*)d_out;

    cudaFuncSetAttribute(pair_kernel,
                         cudaFuncAttributeMaxDynamicSharedMemorySize,
                         PAIR_SMEM_BYTES);

    prep_kernel<<<BHALF / 8, 256>>>(feat);
    pair_kernel<<<PCTAS, 256, PAIR_SMEM_BYTES>>>();
    finalize_kernel<<<16, 512>>>(out);
}